// round 16
// baseline (speedup 1.0000x reference)
#include <cuda_runtime.h>
#include <cuda_fp16.h>
#include <math.h>

#define BB 16384
#define SS 16
#define NSTEPS 50
#define LATENT 128
#define HID 64
#define DTC 0.02f
#define SQRT_DT 0.14142135623730951f
#define LOG2E 1.4426950408889634f
#define LN2 0.6931471805599453f
#define EXPM50 1.9287498479639178e-22f /* exp(-50) */

// Scratch (no cudaMalloc allowed)
__device__ unsigned g_zch[BB * 32]; // per-b hidden bias, f16x2-packed pairs (32 pairs = 64 units)
__device__ float g_halfb[BB];       // 0.5*boundary
__device__ float g_ndt[BB];         // non-decision time

__device__ __forceinline__ float ex2f(float v) {
    float r; asm("ex2.approx.f32 %0, %1;" : "=f"(r) : "f"(v)); return r;
}
__device__ __forceinline__ float lg2f(float v) {
    float r; asm("lg2.approx.f32 %0, %1;" : "=f"(r) : "f"(v)); return r;
}
__device__ __forceinline__ float rcpf(float v) {
    float r; asm("rcp.approx.f32 %0, %1;" : "=f"(r) : "f"(v)); return r;
}
__device__ __forceinline__ float tanhapx(float v) {
    float r; asm("tanh.approx.f32 %0, %1;" : "=f"(r) : "f"(v)); return r;
}
__device__ __forceinline__ half2 tanh2h(half2 x) {
    unsigned xi = *reinterpret_cast<unsigned*>(&x);
    unsigned r;
    asm("tanh.approx.f16x2 %0, %1;" : "=r"(r) : "r"(xi));
    return *reinterpret_cast<half2*>(&r);
}
__device__ __forceinline__ half2 u2h(unsigned v) {
    return *reinterpret_cast<half2*>(&v);
}
__device__ __forceinline__ unsigned h2u(half2 v) {
    return *reinterpret_cast<unsigned*>(&v);
}
// Expand the two f16 halves of v to f32 via ALU-pipe bit-expansion
// (exact for normal f16; subnormals err <= 6.1e-5 abs — negligible here).
__device__ __forceinline__ float h2lo(half2 v) {
    unsigned r = *reinterpret_cast<unsigned*>(&v);
    unsigned lo = ((r << 16) & 0x80000000u) | (((r & 0x7FFFu) << 13) + 0x38000000u);
    return __uint_as_float(lo);
}
__device__ __forceinline__ float h2hi(half2 v) {
    unsigned r = *reinterpret_cast<unsigned*>(&v);
    unsigned hi = (r & 0x80000000u) | (((r >> 3) & 0x0FFFE000u) + 0x38000000u);
    return __uint_as_float(hi);
}
__device__ __forceinline__ float h2sum(half2 v) {
    return h2lo(v) + h2hi(v);
}
__device__ __forceinline__ float fix_out(float v) {
    if (isnan(v)) return 0.0f;
    return fminf(fmaxf(v, -3.402823466e38f), 3.402823466e38f);
}

// ---------------------------------------------------------------------------
// Precompute: zc[b][j] = b1[j] + sum_k z[b,k]*W1[j,2+k], stored f16x2-packed;
// boundary & ndt per b.
// ---------------------------------------------------------------------------
__global__ __launch_bounds__(256) void precompute_kernel(
    const float* __restrict__ z,  const float* __restrict__ W1,
    const float* __restrict__ b1, const float* __restrict__ Wb,
    const float* __restrict__ bbv, const float* __restrict__ Wn,
    const float* __restrict__ bnv)
{
    __shared__ __align__(16) float sW[HID * 130];   // whole W1, 33.3KB
    __shared__ __align__(16) float sz[16 * LATENT]; // 16 z rows, 8KB
    const int tid = threadIdx.x;
    const int b0 = blockIdx.x * 16;

    for (int i = tid; i < HID * 130; i += 256) sW[i] = W1[i];
    for (int i = tid; i < 16 * LATENT; i += 256) sz[i] = z[b0 * LATENT + i];
    __syncthreads();

    const int j = tid & 63;
    const int bg = tid >> 6;   // 0..3, each handles 4 b's
    const float* wrow = sW + j * 130 + 2;
    float a0, a1, a2, a3;
    a0 = a1 = a2 = a3 = b1[j];
    const float* z0 = sz + (bg * 4 + 0) * LATENT;
    const float* z1 = sz + (bg * 4 + 1) * LATENT;
    const float* z2 = sz + (bg * 4 + 2) * LATENT;
    const float* z3 = sz + (bg * 4 + 3) * LATENT;
    #pragma unroll 8
    for (int k = 0; k < LATENT; k += 4) {
        float w0 = wrow[k], w1 = wrow[k + 1], w2 = wrow[k + 2], w3 = wrow[k + 3];
        float4 q0 = *(const float4*)(z0 + k);
        float4 q1 = *(const float4*)(z1 + k);
        float4 q2 = *(const float4*)(z2 + k);
        float4 q3 = *(const float4*)(z3 + k);
        a0 = fmaf(w0, q0.x, a0); a0 = fmaf(w1, q0.y, a0); a0 = fmaf(w2, q0.z, a0); a0 = fmaf(w3, q0.w, a0);
        a1 = fmaf(w0, q1.x, a1); a1 = fmaf(w1, q1.y, a1); a1 = fmaf(w2, q1.z, a1); a1 = fmaf(w3, q1.w, a1);
        a2 = fmaf(w0, q2.x, a2); a2 = fmaf(w1, q2.y, a2); a2 = fmaf(w2, q2.z, a2); a2 = fmaf(w3, q2.w, a2);
        a3 = fmaf(w0, q3.x, a3); a3 = fmaf(w1, q3.y, a3); a3 = fmaf(w2, q3.z, a3); a3 = fmaf(w3, q3.w, a3);
    }

    // pack (j, j+1) pairs into f16x2 via partner shuffle; even j stores
    const float p0 = __shfl_xor_sync(0xffffffffu, a0, 1);
    const float p1 = __shfl_xor_sync(0xffffffffu, a1, 1);
    const float p2 = __shfl_xor_sync(0xffffffffu, a2, 1);
    const float p3 = __shfl_xor_sync(0xffffffffu, a3, 1);
    if ((j & 1) == 0) {
        const int col = j >> 1;   // 0..31
        half2 h0 = __floats2half2_rn(a0, p0);
        half2 h1 = __floats2half2_rn(a1, p1);
        half2 h2v = __floats2half2_rn(a2, p2);
        half2 h3 = __floats2half2_rn(a3, p3);
        g_zch[(b0 + bg * 4 + 0) * 32 + col] = h2u(h0);
        g_zch[(b0 + bg * 4 + 1) * 32 + col] = h2u(h1);
        g_zch[(b0 + bg * 4 + 2) * 32 + col] = h2u(h2v);
        g_zch[(b0 + bg * 4 + 3) * 32 + col] = h2u(h3);
    }

    if (tid < 32) {
        const int bl = tid >> 1;
        const int isn = tid & 1;
        const float* wv = isn ? Wn : Wb;
        const float* zz = sz + bl * LATENT;
        float acc = isn ? bnv[0] : bbv[0];
        #pragma unroll 8
        for (int k = 0; k < LATENT; k++) acc = fmaf(wv[k], zz[k], acc);
        float sp = fmaxf(acc, 0.0f) + log1pf(expf(-fabsf(acc)));
        if (isn) g_ndt[b0 + bl] = sp + 0.05f;
        else     g_halfb[b0 + bl] = 0.5f * (sp + 0.3f);
    }
}

// Padé tanh for one packed pair: tanh(u) ~= u(945+105u^2+u^4)/(945+420u^2+15u^4),
// u clamped to [-4,4], result clamped to [-1,1]. One MUFU rcp serves BOTH
// halves: r = rcp(dlo*dhi); 1/dlo = r*dhi. Everything else fma/alu-pipe.
__device__ __forceinline__ half2 tanh_pade(half2 u, half2 c105, half2 c945,
                                           half2 c420, half2 c15,
                                           half2 hp4, half2 hm4) {
    u = __hmin2(__hmax2(u, hm4), hp4);
    const half2 s   = __hmul2(u, u);
    const half2 num = __hfma2(s, __hadd2(s, c105), c945);
    const half2 den = __hfma2(s, __hfma2(s, c15, c420), c945);
    const half2 xn  = __hmul2(u, num);
    const float dlo = h2lo(den), dhi = h2hi(den);
    const float r   = rcpf(dlo * dhi);
    float hlo = h2lo(xn) * (r * dhi);
    float hhi = h2hi(xn) * (r * dlo);
    hlo = fminf(fmaxf(hlo, -1.0f), 1.0f);
    hhi = fminf(fmaxf(hhi, -1.0f), 1.0f);
    return __floats2half2_rn(hlo, hhi);
}

// ---------------------------------------------------------------------------
// Main SDE kernel. Structure identical to R15 (lane pair serves 2 sims of one
// b; 16 unit-pairs per lane in registers; parity-split tails; packed-f16
// exchanges). NEW: hidden-unit pairs 12..15 evaluate tanh via the fma-pipe
// Padé rational (1 shared MUFU rcp per pair-sim) instead of tanh.approx.f16x2
// (2 MUFU slots each) — cutting the per-warp-step MUFU slot count 67 -> 59,
// the measured roofline. Block 64, 9 blocks/SM.
// ---------------------------------------------------------------------------
__global__ __launch_bounds__(64, 9) void sde_kernel(
    const float* __restrict__ W1, const float* __restrict__ W2,
    const float* __restrict__ b2, const float* __restrict__ noise,
    const float* __restrict__ osc, const float* __restrict__ obi,
    float* __restrict__ out)
{
    const int tid  = threadIdx.x;
    const int lane = tid & 31;
    const int wrp  = tid >> 5;        // warp 0..1
    const int q    = lane >> 1;       // pair 0..15
    const int half = lane & 1;        // unit-half AND tail-parity
    const int b    = blockIdx.x * 4 + wrp * 2 + (q >> 3);
    const int jbase = half * 32;

    // weights: 16 f16x2 pairs each = 80 u32 regs
    half2 w1x2[16], w1t2[16], zc2[16], w2a2[16], w2b2[16];
    #pragma unroll
    for (int p = 0; p < 16; p++) {
        const int j = jbase + p * 2;
        w1x2[p] = __floats2half2_rn(W1[j * 130],     W1[(j + 1) * 130]);
        w1t2[p] = __floats2half2_rn(W1[j * 130 + 1], W1[(j + 1) * 130 + 1]);
        zc2[p]  = u2h(g_zch[b * 32 + half * 16 + p]);
        w2a2[p] = __floats2half2_rn(W2[j],       W2[j + 1]);
        w2b2[p] = __floats2half2_rn(W2[HID + j], W2[HID + j + 1]);
    }
    const float b2x = b2[0], b2y = b2[1];
    const float half_b = g_halfb[b];
    const half2 hzero = __floats2half2_rn(0.0f, 0.0f);
    const half2 c105 = __float2half2_rn(105.0f);
    const half2 c945 = __float2half2_rn(945.0f);
    const half2 c420 = __float2half2_rn(420.0f);
    const half2 c15  = __float2half2_rn(15.0f);
    const half2 hp4  = __float2half2_rn(4.0f);
    const half2 hm4  = __float2half2_rn(-4.0f);

    // my sim: even lane -> sA = q&7; odd lane -> sA+8
    const int nidx = b * SS + (q & 7) + half * 8;
    float x_my = 0.0f, p_my = 1.0f, rt_my = 0.0f, cr_my = 0.0f;
    float nz_my = noise[nidx];

    #pragma unroll 1
    for (int k = 0; k < NSTEPS; k++) {
        const int k1 = (k + 1 < NSTEPS) ? (k + 1) : (NSTEPS - 1);
        const float nz_next = noise[k1 * (BB * SS) + nidx];
        const float tk = (float)k * DTC;
        const half2 tkh = __float2half2_rn(tk);

        // exchange x's in packed f16 (both halves carry my x)
        const unsigned xs = h2u(__float2half2_rn(x_my));
        const unsigned xr = __shfl_xor_sync(0xffffffffu, xs, 1);
        const half2 xhA = u2h(half ? xr : xs);
        const half2 xhB = u2h(half ? xs : xr);

        half2 daA = hzero, dbA = hzero, daB = hzero, dbB = hzero;
        // pairs 0..11: MUFU tanh.approx.f16x2
        #pragma unroll
        for (int p = 0; p < 12; p++) {
            const half2 base = __hfma2(tkh, w1t2[p], zc2[p]);   // shared A/B
            const half2 uA = __hfma2(xhA, w1x2[p], base);
            const half2 uB = __hfma2(xhB, w1x2[p], base);
            const half2 hA = tanh2h(uA);
            const half2 hB = tanh2h(uB);
            daA = __hfma2(hA, w2a2[p], daA);
            dbA = __hfma2(hA, w2b2[p], dbA);
            daB = __hfma2(hB, w2a2[p], daB);
            dbB = __hfma2(hB, w2b2[p], dbB);
        }
        // pairs 12..15: fma-pipe Padé tanh (1 MUFU rcp per pair-sim)
        #pragma unroll
        for (int p = 12; p < 16; p++) {
            const half2 base = __hfma2(tkh, w1t2[p], zc2[p]);
            const half2 uA = __hfma2(xhA, w1x2[p], base);
            const half2 uB = __hfma2(xhB, w1x2[p], base);
            const half2 hA = tanh_pade(uA, c105, c945, c420, c15, hp4, hm4);
            const half2 hB = tanh_pade(uB, c105, c945, c420, c15, hp4, hm4);
            daA = __hfma2(hA, w2a2[p], daA);
            dbA = __hfma2(hA, w2b2[p], dbA);
            daB = __hfma2(hB, w2a2[p], daB);
            dbB = __hfma2(hB, w2b2[p], dbB);
        }
        // packed-f16 exchange: even sends its B-partials, odd its A-partials
        const unsigned da_send = half ? h2u(daA) : h2u(daB);
        const unsigned db_send = half ? h2u(dbA) : h2u(dbB);
        const unsigned da_recv = __shfl_xor_sync(0xffffffffu, da_send, 1);
        const unsigned db_recv = __shfl_xor_sync(0xffffffffu, db_send, 1);
        const half2 myda = __hadd2(half ? daB : daA, u2h(da_recv));
        const half2 mydb = __hadd2(half ? dbB : dbA, u2h(db_recv));
        const float pd = h2sum(myda);
        const float pf = h2sum(mydb);

        // --- tail for MY sim only ---
        const float dyn0 = pd + b2x;
        const float dyn1 = pf + b2y;
        const float drift = fminf(fmaxf(dyn0, -5.0f), 5.0f);
        const float e1 = ex2f(-fabsf(dyn1) * LOG2E);
        const float spv = fmaxf(dyn1, 0.0f) + lg2f(1.0f + e1) * LN2;
        const float diff = spv + 0.1f;
        x_my = fmaf(diff * SQRT_DT, nz_my, fmaf(drift, DTC, x_my));
        x_my = fminf(fmaxf(x_my, -10.0f), 10.0f);
        const float dist = fabsf(x_my) - half_b;
        const float sg = fmaf(0.5f, tanhapx(10.0f * dist), 0.5f);
        const float hz = fminf(fmaxf(sg, 0.0f), 0.99f);
        const float sb = fmaxf(p_my, EXPM50);
        const float cp = sb * hz;
        p_my = p_my * (1.0f - hz);
        rt_my = fmaf(cp, tk + DTC, rt_my);
        cr_my += (x_my > 0.0f) ? cp : 0.0f;

        nz_my = nz_next;
    }

    const float rem = fmaxf(p_my, EXPM50);
    rt_my = fmaf(rem, (float)NSTEPS * DTC, rt_my);
    cr_my = fmaf(rem, 0.5f, cr_my);
    const float rtms = (rt_my + g_ndt[b]) * 1000.0f;

    // stats per b: each of the 16 lanes of a b-group owns exactly one sim
    float srt = rtms;
    float scr = cr_my;
    #pragma unroll
    for (int off = 1; off < 16; off <<= 1) {
        srt += __shfl_xor_sync(0xffffffffu, srt, off);
        scr += __shfl_xor_sync(0xffffffffu, scr, off);
    }
    const float m = srt * (1.0f / 16.0f);
    const float c = scr * (1.0f / 16.0f);
    const float d = rtms - m;
    float v = d * d;
    #pragma unroll
    for (int off = 1; off < 16; off <<= 1) {
        v += __shfl_xor_sync(0xffffffffu, v, off);
    }

    if ((lane & 15) == 0) {
        const float sd = sqrtf(v * (1.0f / 15.0f));  // ddof=1
        const float o0 = m * osc[0] + obi[0];
        const float o1 = (sd + 0.001f) * osc[1] + obi[1];
        const float o2 = c * osc[2] + obi[2];
        out[b * 3 + 0] = fix_out(o0);
        out[b * 3 + 1] = fix_out(o1);
        out[b * 3 + 2] = fix_out(o2);
    }
}

extern "C" void kernel_launch(void* const* d_in, const int* in_sizes, int n_in,
                              void* d_out, int out_size)
{
    const float* z   = (const float*)d_in[0];
    const float* W1  = (const float*)d_in[1];
    const float* b1  = (const float*)d_in[2];
    const float* W2  = (const float*)d_in[3];
    const float* b2  = (const float*)d_in[4];
    const float* Wb  = (const float*)d_in[5];
    const float* bbv = (const float*)d_in[6];
    const float* Wn  = (const float*)d_in[7];
    const float* bnv = (const float*)d_in[8];
    const float* osc = (const float*)d_in[9];
    const float* obi = (const float*)d_in[10];
    const float* noise = (const float*)d_in[11];
    float* out = (float*)d_out;

    precompute_kernel<<<BB / 16, 256>>>(z, W1, b1, Wb, bbv, Wn, bnv);
    sde_kernel<<<BB / 4, 64>>>(W1, W2, b2, noise, osc, obi, out);
}

// round 17
// speedup vs baseline: 1.2907x; 1.2907x over previous
#include <cuda_runtime.h>
#include <cuda_fp16.h>
#include <math.h>

#define BB 16384
#define SS 16
#define NSTEPS 50
#define LATENT 128
#define HID 64
#define DTC 0.02f
#define SQRT_DT 0.14142135623730951f
#define LOG2E 1.4426950408889634f
#define LN2 0.6931471805599453f
#define EXPM50 1.9287498479639178e-22f /* exp(-50) */

// Scratch (no cudaMalloc allowed)
__device__ unsigned g_zch[BB * 32]; // per-b hidden bias, f16x2-packed pairs (32 pairs = 64 units)
__device__ float g_halfb[BB];       // 0.5*boundary
__device__ float g_ndt[BB];         // non-decision time

__device__ __forceinline__ float ex2f(float v) {
    float r; asm("ex2.approx.f32 %0, %1;" : "=f"(r) : "f"(v)); return r;
}
__device__ __forceinline__ float lg2f(float v) {
    float r; asm("lg2.approx.f32 %0, %1;" : "=f"(r) : "f"(v)); return r;
}
__device__ __forceinline__ float tanhapx(float v) {
    float r; asm("tanh.approx.f32 %0, %1;" : "=f"(r) : "f"(v)); return r;
}
__device__ __forceinline__ half2 tanh2h(half2 x) {
    unsigned xi = *reinterpret_cast<unsigned*>(&x);
    unsigned r;
    asm("tanh.approx.f16x2 %0, %1;" : "=r"(r) : "r"(xi));
    return *reinterpret_cast<half2*>(&r);
}
__device__ __forceinline__ half2 u2h(unsigned v) {
    return *reinterpret_cast<half2*>(&v);
}
__device__ __forceinline__ unsigned h2u(half2 v) {
    return *reinterpret_cast<unsigned*>(&v);
}
// Sum the two f16 halves of v as f32, using ALU-pipe bit-expansion
// (exact for normal f16; subnormals introduce <= 6.1e-5 abs error).
__device__ __forceinline__ float h2sum(half2 v) {
    unsigned r = *reinterpret_cast<unsigned*>(&v);
    unsigned lo = ((r << 16) & 0x80000000u) | (((r & 0x7FFFu) << 13) + 0x38000000u);
    unsigned hi = (r & 0x80000000u) | (((r >> 3) & 0x0FFFE000u) + 0x38000000u);
    return __uint_as_float(lo) + __uint_as_float(hi);
}
__device__ __forceinline__ float fix_out(float v) {
    if (isnan(v)) return 0.0f;
    return fminf(fmaxf(v, -3.402823466e38f), 3.402823466e38f);
}

// ---------------------------------------------------------------------------
// Precompute: zc[b][j] = b1[j] + sum_k z[b,k]*W1[j,2+k], stored f16x2-packed;
// boundary & ndt per b.
// ---------------------------------------------------------------------------
__global__ __launch_bounds__(256) void precompute_kernel(
    const float* __restrict__ z,  const float* __restrict__ W1,
    const float* __restrict__ b1, const float* __restrict__ Wb,
    const float* __restrict__ bbv, const float* __restrict__ Wn,
    const float* __restrict__ bnv)
{
    __shared__ __align__(16) float sW[HID * 130];   // whole W1, 33.3KB
    __shared__ __align__(16) float sz[16 * LATENT]; // 16 z rows, 8KB
    const int tid = threadIdx.x;
    const int b0 = blockIdx.x * 16;

    for (int i = tid; i < HID * 130; i += 256) sW[i] = W1[i];
    for (int i = tid; i < 16 * LATENT; i += 256) sz[i] = z[b0 * LATENT + i];
    __syncthreads();

    const int j = tid & 63;
    const int bg = tid >> 6;   // 0..3, each handles 4 b's
    const float* wrow = sW + j * 130 + 2;
    float a0, a1, a2, a3;
    a0 = a1 = a2 = a3 = b1[j];
    const float* z0 = sz + (bg * 4 + 0) * LATENT;
    const float* z1 = sz + (bg * 4 + 1) * LATENT;
    const float* z2 = sz + (bg * 4 + 2) * LATENT;
    const float* z3 = sz + (bg * 4 + 3) * LATENT;
    #pragma unroll 8
    for (int k = 0; k < LATENT; k += 4) {
        float w0 = wrow[k], w1 = wrow[k + 1], w2 = wrow[k + 2], w3 = wrow[k + 3];
        float4 q0 = *(const float4*)(z0 + k);
        float4 q1 = *(const float4*)(z1 + k);
        float4 q2 = *(const float4*)(z2 + k);
        float4 q3 = *(const float4*)(z3 + k);
        a0 = fmaf(w0, q0.x, a0); a0 = fmaf(w1, q0.y, a0); a0 = fmaf(w2, q0.z, a0); a0 = fmaf(w3, q0.w, a0);
        a1 = fmaf(w0, q1.x, a1); a1 = fmaf(w1, q1.y, a1); a1 = fmaf(w2, q1.z, a1); a1 = fmaf(w3, q1.w, a1);
        a2 = fmaf(w0, q2.x, a2); a2 = fmaf(w1, q2.y, a2); a2 = fmaf(w2, q2.z, a2); a2 = fmaf(w3, q2.w, a2);
        a3 = fmaf(w0, q3.x, a3); a3 = fmaf(w1, q3.y, a3); a3 = fmaf(w2, q3.z, a3); a3 = fmaf(w3, q3.w, a3);
    }

    // pack (j, j+1) pairs into f16x2 via partner shuffle; even j stores
    const float p0 = __shfl_xor_sync(0xffffffffu, a0, 1);
    const float p1 = __shfl_xor_sync(0xffffffffu, a1, 1);
    const float p2 = __shfl_xor_sync(0xffffffffu, a2, 1);
    const float p3 = __shfl_xor_sync(0xffffffffu, a3, 1);
    if ((j & 1) == 0) {
        const int col = j >> 1;   // 0..31
        half2 h0 = __floats2half2_rn(a0, p0);
        half2 h1 = __floats2half2_rn(a1, p1);
        half2 h2v = __floats2half2_rn(a2, p2);
        half2 h3 = __floats2half2_rn(a3, p3);
        g_zch[(b0 + bg * 4 + 0) * 32 + col] = h2u(h0);
        g_zch[(b0 + bg * 4 + 1) * 32 + col] = h2u(h1);
        g_zch[(b0 + bg * 4 + 2) * 32 + col] = h2u(h2v);
        g_zch[(b0 + bg * 4 + 3) * 32 + col] = h2u(h3);
    }

    if (tid < 32) {
        const int bl = tid >> 1;
        const int isn = tid & 1;
        const float* wv = isn ? Wn : Wb;
        const float* zz = sz + bl * LATENT;
        float acc = isn ? bnv[0] : bbv[0];
        #pragma unroll 8
        for (int k = 0; k < LATENT; k++) acc = fmaf(wv[k], zz[k], acc);
        float sp = fmaxf(acc, 0.0f) + log1pf(expf(-fabsf(acc)));
        if (isn) g_ndt[b0 + bl] = sp + 0.05f;
        else     g_halfb[b0 + bl] = 0.5f * (sp + 0.3f);
    }
}

// ---------------------------------------------------------------------------
// Main SDE kernel. Bit-identical math to the 238us R15 kernel; only the
// launch shape changes: ONE WARP PER BLOCK (32 threads, 21 blocks/SM) for
// finer wave granularity (work-steal smooths the tail wave) and higher
// register-limited occupancy (18 -> ~21 warps/SM).
// Lane pair (2q, 2q+1) serves two sims of one b; each lane owns 32 of 64
// hidden units (16 f16x2 pairs, ALL weights in registers) and evaluates BOTH
// sims' hidden layers (shared base HFMA2), but owns the tail and survival
// state of only ONE sim (even lane -> sim q&7, odd lane -> (q&7)+8).
// x and dot-partials exchanged as packed f16. Warp = 32 sims = 2 b's.
// ---------------------------------------------------------------------------
__global__ __launch_bounds__(32, 21) void sde_kernel(
    const float* __restrict__ W1, const float* __restrict__ W2,
    const float* __restrict__ b2, const float* __restrict__ noise,
    const float* __restrict__ osc, const float* __restrict__ obi,
    float* __restrict__ out)
{
    const int lane = threadIdx.x & 31;
    const int q    = lane >> 1;       // pair 0..15
    const int half = lane & 1;        // unit-half AND tail-parity
    const int b    = blockIdx.x * 2 + (q >> 3);
    const int jbase = half * 32;

    // weights: 16 f16x2 pairs each = 80 u32 regs
    half2 w1x2[16], w1t2[16], zc2[16], w2a2[16], w2b2[16];
    #pragma unroll
    for (int p = 0; p < 16; p++) {
        const int j = jbase + p * 2;
        w1x2[p] = __floats2half2_rn(W1[j * 130],     W1[(j + 1) * 130]);
        w1t2[p] = __floats2half2_rn(W1[j * 130 + 1], W1[(j + 1) * 130 + 1]);
        zc2[p]  = u2h(g_zch[b * 32 + half * 16 + p]);
        w2a2[p] = __floats2half2_rn(W2[j],       W2[j + 1]);
        w2b2[p] = __floats2half2_rn(W2[HID + j], W2[HID + j + 1]);
    }
    const float b2x = b2[0], b2y = b2[1];
    const float half_b = g_halfb[b];
    const half2 hzero = __floats2half2_rn(0.0f, 0.0f);

    // my sim: even lane -> sA = q&7; odd lane -> sA+8
    const int nidx = b * SS + (q & 7) + half * 8;
    float x_my = 0.0f, p_my = 1.0f, rt_my = 0.0f, cr_my = 0.0f;
    float nz_my = noise[nidx];

    #pragma unroll 1
    for (int k = 0; k < NSTEPS; k++) {
        const int k1 = (k + 1 < NSTEPS) ? (k + 1) : (NSTEPS - 1);
        const float nz_next = noise[k1 * (BB * SS) + nidx];
        const float tk = (float)k * DTC;
        const half2 tkh = __float2half2_rn(tk);

        // exchange x's in packed f16 (both halves carry my x)
        const unsigned xs = h2u(__float2half2_rn(x_my));
        const unsigned xr = __shfl_xor_sync(0xffffffffu, xs, 1);
        const half2 xhA = u2h(half ? xr : xs);
        const half2 xhB = u2h(half ? xs : xr);

        half2 daA = hzero, dbA = hzero, daB = hzero, dbB = hzero;
        #pragma unroll
        for (int p = 0; p < 16; p++) {
            const half2 base = __hfma2(tkh, w1t2[p], zc2[p]);   // shared A/B
            const half2 uA = __hfma2(xhA, w1x2[p], base);
            const half2 uB = __hfma2(xhB, w1x2[p], base);
            const half2 hA = tanh2h(uA);
            const half2 hB = tanh2h(uB);
            daA = __hfma2(hA, w2a2[p], daA);
            dbA = __hfma2(hA, w2b2[p], dbA);
            daB = __hfma2(hB, w2a2[p], daB);
            dbB = __hfma2(hB, w2b2[p], dbB);
        }
        // packed-f16 exchange: even sends its B-partials, odd its A-partials
        const unsigned da_send = half ? h2u(daA) : h2u(daB);
        const unsigned db_send = half ? h2u(dbA) : h2u(dbB);
        const unsigned da_recv = __shfl_xor_sync(0xffffffffu, da_send, 1);
        const unsigned db_recv = __shfl_xor_sync(0xffffffffu, db_send, 1);
        const half2 myda = __hadd2(half ? daB : daA, u2h(da_recv));
        const half2 mydb = __hadd2(half ? dbB : dbA, u2h(db_recv));
        const float pd = h2sum(myda);
        const float pf = h2sum(mydb);

        // --- tail for MY sim only ---
        const float dyn0 = pd + b2x;
        const float dyn1 = pf + b2y;
        const float drift = fminf(fmaxf(dyn0, -5.0f), 5.0f);
        const float e1 = ex2f(-fabsf(dyn1) * LOG2E);
        const float spv = fmaxf(dyn1, 0.0f) + lg2f(1.0f + e1) * LN2;
        const float diff = spv + 0.1f;
        x_my = fmaf(diff * SQRT_DT, nz_my, fmaf(drift, DTC, x_my));
        x_my = fminf(fmaxf(x_my, -10.0f), 10.0f);
        const float dist = fabsf(x_my) - half_b;
        const float sg = fmaf(0.5f, tanhapx(10.0f * dist), 0.5f);
        const float hz = fminf(fmaxf(sg, 0.0f), 0.99f);
        const float sb = fmaxf(p_my, EXPM50);
        const float cp = sb * hz;
        p_my = p_my * (1.0f - hz);
        rt_my = fmaf(cp, tk + DTC, rt_my);
        cr_my += (x_my > 0.0f) ? cp : 0.0f;

        nz_my = nz_next;
    }

    const float rem = fmaxf(p_my, EXPM50);
    rt_my = fmaf(rem, (float)NSTEPS * DTC, rt_my);
    cr_my = fmaf(rem, 0.5f, cr_my);
    const float rtms = (rt_my + g_ndt[b]) * 1000.0f;

    // stats per b: each of the 16 lanes of a b-group owns exactly one sim
    float srt = rtms;
    float scr = cr_my;
    #pragma unroll
    for (int off = 1; off < 16; off <<= 1) {
        srt += __shfl_xor_sync(0xffffffffu, srt, off);
        scr += __shfl_xor_sync(0xffffffffu, scr, off);
    }
    const float m = srt * (1.0f / 16.0f);
    const float c = scr * (1.0f / 16.0f);
    const float d = rtms - m;
    float v = d * d;
    #pragma unroll
    for (int off = 1; off < 16; off <<= 1) {
        v += __shfl_xor_sync(0xffffffffu, v, off);
    }

    if ((lane & 15) == 0) {
        const float sd = sqrtf(v * (1.0f / 15.0f));  // ddof=1
        const float o0 = m * osc[0] + obi[0];
        const float o1 = (sd + 0.001f) * osc[1] + obi[1];
        const float o2 = c * osc[2] + obi[2];
        out[b * 3 + 0] = fix_out(o0);
        out[b * 3 + 1] = fix_out(o1);
        out[b * 3 + 2] = fix_out(o2);
    }
}

extern "C" void kernel_launch(void* const* d_in, const int* in_sizes, int n_in,
                              void* d_out, int out_size)
{
    const float* z   = (const float*)d_in[0];
    const float* W1  = (const float*)d_in[1];
    const float* b1  = (const float*)d_in[2];
    const float* W2  = (const float*)d_in[3];
    const float* b2  = (const float*)d_in[4];
    const float* Wb  = (const float*)d_in[5];
    const float* bbv = (const float*)d_in[6];
    const float* Wn  = (const float*)d_in[7];
    const float* bnv = (const float*)d_in[8];
    const float* osc = (const float*)d_in[9];
    const float* obi = (const float*)d_in[10];
    const float* noise = (const float*)d_in[11];
    float* out = (float*)d_out;

    precompute_kernel<<<BB / 16, 256>>>(z, W1, b1, Wb, bbv, Wn, bnv);
    sde_kernel<<<BB / 2, 32>>>(W1, W2, b2, noise, osc, obi, out);
}